// round 13
// baseline (speedup 1.0000x reference)
#include <cuda_runtime.h>
#include <cuda_bf16.h>
#include <math.h>

// Problem constants: n=100, h=16, w=16, f_in=8, f_out=16
#define N_NODES 100
#define PIX 256
#define FIN 8
#define FOUT 16
#define ALPHA 0.2f

#define TI 4     // nodes per k23 block
#define DST 33   // D smem stride (conflict-free lane-j reads)
#define AST 20   // att smem stride per (ii,j) row (16B-aligned, 4-way STS)

// Device scratch
__device__ __align__(16) float g_Wh[N_NODES * PIX * FOUT];   // [j][pixel][c]  1.6MB
__device__ float g_D[N_NODES * 32];                          // [i][y*2+dy]

// packed f32x2 helpers (sm_100+)
__device__ __forceinline__ unsigned long long pack2(float lo, float hi) {
    unsigned long long r;
    asm("mov.b64 %0, {%1,%2};" : "=l"(r) : "f"(lo), "f"(hi));
    return r;
}
__device__ __forceinline__ void unpack2(float& lo, float& hi, unsigned long long v) {
    asm("mov.b64 {%0,%1}, %2;" : "=f"(lo), "=f"(hi) : "l"(v));
}
#define FMA2(d, a, b, c) asm("fma.rn.f32x2 %0, %1, %2, %3;" : "=l"(d) : "l"(a), "l"(b), "l"(c))

// ---------------------------------------------------------------------------
// Kernel 1: Wh = x @ W ; D[i,y,dy] = sum_{x,c} Wh[i,y,x,c] * a[dy*256+x*16+c]
// grid 100 (i), block 256 (pixel)   [R5 body, measured ~5.2-5.6us]
// ---------------------------------------------------------------------------
__global__ __launch_bounds__(256) void k_wh_d(const float* __restrict__ x,
                                              const float* __restrict__ W,
                                              const float* __restrict__ a)
{
    __shared__ float W_s[FIN * FOUT];
    __shared__ float a_s[512];

    const int i = blockIdx.x;
    const int p = threadIdx.x;

    if (p < FIN * FOUT) W_s[p] = W[p];
    a_s[p]       = a[p];
    a_s[p + 256] = a[p + 256];
    __syncthreads();

    const float4* xp = reinterpret_cast<const float4*>(x) + (size_t)(i * PIX + p) * 2;
    float4 x0 = xp[0];
    float4 x1 = xp[1];
    float xv[8] = {x0.x, x0.y, x0.z, x0.w, x1.x, x1.y, x1.z, x1.w};

    float wh[FOUT];
#pragma unroll
    for (int c = 0; c < FOUT; ++c) {
        float s = 0.f;
#pragma unroll
        for (int k = 0; k < FIN; ++k) s += xv[k] * W_s[k * FOUT + c];
        wh[c] = s;
    }

    float4* whp = reinterpret_cast<float4*>(g_Wh) + (size_t)(i * PIX + p) * 4;
    whp[0] = make_float4(wh[0],  wh[1],  wh[2],  wh[3]);
    whp[1] = make_float4(wh[4],  wh[5],  wh[6],  wh[7]);
    whp[2] = make_float4(wh[8],  wh[9],  wh[10], wh[11]);
    whp[3] = make_float4(wh[12], wh[13], wh[14], wh[15]);

    const int xx = p & 15;
    float pd0 = 0.f, pd1 = 0.f;
#pragma unroll
    for (int c = 0; c < FOUT; ++c) {
        pd0 += wh[c] * a_s[xx * 16 + c];
        pd1 += wh[c] * a_s[256 + xx * 16 + c];
    }
#pragma unroll
    for (int off = 8; off >= 1; off >>= 1) {
        pd0 += __shfl_xor_sync(0xffffffffu, pd0, off, 16);
        pd1 += __shfl_xor_sync(0xffffffffu, pd1, off, 16);
    }
    if (xx == 0) {
        const int y = p >> 4;
        g_D[i * 32 + 2 * y]     = pd0;
        g_D[i * 32 + 2 * y + 1] = pd1;
    }
}

// ---------------------------------------------------------------------------
// Kernel 2 (fused att + h'): grid 100 = (25 i-tiles x 4 pixel-quarters),
// block 512 (16 warps). __launch_bounds__(512, 1) -> up to 128 regs, NO SPILLS.
// Phase B: 4 softmaxes per warp -> att in smem (stride 20).
// Phase C: warp = (cg, ii-pair, pixel-half); unroll-4 j loop, f32x2 FMAs.
// smem: 13.2KB (D) + 32KB (att) = 45.2KB static.
// ---------------------------------------------------------------------------
__global__ __launch_bounds__(512, 1) void k23(const int* __restrict__ adj,
                                              float* __restrict__ out)
{
    __shared__ __align__(16) float D_s[N_NODES * DST];        // 13.2KB
    __shared__ __align__(16) float att_s[TI * N_NODES * AST]; // 32.0KB

    const int b   = blockIdx.x;
    const int tid = threadIdx.x;
    const int w   = tid >> 5;
    const int l   = tid & 31;
    const int i0  = (b >> 2) * TI;    // i-tile base
    const int p0  = (b & 3) * 64;     // pixel-quarter base

    // ---- stage D (coalesced, padded) ----
    for (int q = tid; q < N_NODES * 32; q += 512)
        D_s[(q >> 5) * DST + (q & 31)] = g_D[q];
    __syncthreads();

    // ---- Phase B: 64 softmaxes (4 nodes x 16 channels), 4 per warp ----
#pragma unroll
    for (int s = 0; s < 4; ++s) {
        const int idx = s * 16 + w;       // 0..63
        const int ii  = idx >> 4;
        const int c   = idx & 15;
        const float* Di   = &D_s[(i0 + ii) * DST];
        const int*   arow = adj + (size_t)(i0 + ii) * N_NODES;

        float ev[4];
        float mx = -3.4e38f;
#pragma unroll
        for (int t = 0; t < 4; ++t) {
            const int j = l + 32 * t;
            if (j < N_NODES) {
                float e;
                if (c < 8) {
                    const int bb = 16 * j + 2 * c;
                    e = Di[(bb / 100) * 2] + Di[((bb + 1) / 100) * 2 + 1];
                } else {
                    const int r2 = 2 * c - 16;
                    e = D_s[j * DST + 2 * r2] + D_s[j * DST + 2 * r2 + 3];
                }
                e = (e > 0.f) ? e : ALPHA * e;
                e = (arow[j] > 0) ? e : -9e15f;
                ev[t] = e;
                mx = fmaxf(mx, e);
            } else {
                ev[t] = -3.4e38f;
            }
        }
#pragma unroll
        for (int off = 16; off >= 1; off >>= 1)
            mx = fmaxf(mx, __shfl_xor_sync(0xffffffffu, mx, off));

        float sum = 0.f;
#pragma unroll
        for (int t = 0; t < 4; ++t) {
            const int j = l + 32 * t;
            if (j < N_NODES) {
                ev[t] = __expf(ev[t] - mx);
                sum += ev[t];
            }
        }
#pragma unroll
        for (int off = 16; off >= 1; off >>= 1)
            sum += __shfl_xor_sync(0xffffffffu, sum, off);

        const float inv = 1.0f / sum;
#pragma unroll
        for (int t = 0; t < 4; ++t) {
            const int j = l + 32 * t;
            if (j < N_NODES)
                att_s[(ii * N_NODES + j) * AST + c] = ev[t] * inv;
        }
    }
    __syncthreads();

    // ---- Phase C: h'[i0+ii, pixel, 4cg..4cg+4) = sum_j att * Wh ----
    // 16 warps: cg = w&3, iip = (w>>2)&1 (ii in {2iip, 2iip+1}), psub = w>>3
    const int cg    = w & 3;
    const int iib   = ((w >> 2) & 1) * 2;
    const int psub  = w >> 3;
    const int pixel = p0 + psub * 32 + l;

    unsigned long long acc0[2], acc1[2];
    const unsigned long long z = pack2(0.f, 0.f);
    acc0[0] = z; acc1[0] = z; acc0[1] = z; acc1[1] = z;

    const ulonglong2* wh2 = reinterpret_cast<const ulonglong2*>(g_Wh) +
                            (size_t)pixel * 4 + cg;
    // per-warp att bases, hoisted out of the j loop
    const ulonglong2* at2a = reinterpret_cast<const ulonglong2*>(att_s) +
                             (size_t)iib * N_NODES * 5 + cg;
    const ulonglong2* at2b = at2a + (size_t)N_NODES * 5;

#pragma unroll 4
    for (int j = 0; j < N_NODES; ++j) {
        const ulonglong2 whp = wh2[(size_t)j * (PIX * 4)];
        const ulonglong2 apa = at2a[(size_t)j * 5];   // warp-uniform broadcast
        const ulonglong2 apb = at2b[(size_t)j * 5];
        FMA2(acc0[0], apa.x, whp.x, acc0[0]);
        FMA2(acc1[0], apa.y, whp.y, acc1[0]);
        FMA2(acc0[1], apb.x, whp.x, acc0[1]);
        FMA2(acc1[1], apb.y, whp.y, acc1[1]);
    }

#pragma unroll
    for (int u = 0; u < 2; ++u) {
        float f0, f1, f2, f3;
        unpack2(f0, f1, acc0[u]);
        unpack2(f2, f3, acc1[u]);
        reinterpret_cast<float4*>(out)[((i0 + iib + u) * PIX + pixel) * 4 + cg] =
            make_float4(f0, f1, f2, f3);
    }
}

// ---------------------------------------------------------------------------
extern "C" void kernel_launch(void* const* d_in, const int* in_sizes, int n_in,
                              void* d_out, int out_size)
{
    const float* x   = (const float*)d_in[0];
    const int*   adj = (const int*)d_in[1];
    const float* W   = (const float*)d_in[2];
    const float* a   = (const float*)d_in[3];
    float* out = (float*)d_out;

    k_wh_d<<<N_NODES, 256>>>(x, W, a);
    k23<<<N_NODES, 512>>>(adj, out);
}

// round 14
// speedup vs baseline: 1.0962x; 1.0962x over previous
#include <cuda_runtime.h>
#include <cuda_bf16.h>
#include <math.h>

// Problem constants: n=100, h=16, w=16, f_in=8, f_out=16
#define N_NODES 100
#define PIX 256
#define FIN 8
#define FOUT 16
#define ALPHA 0.2f

// Device scratch
__device__ __align__(16) float g_Wh[N_NODES * PIX * FOUT];       // [j][pixel][c]  1.6MB
__device__ float g_D[N_NODES * 32];                              // [i][y*2+dy]
__device__ __align__(16) float g_att[N_NODES * N_NODES * FOUT];  // [i][j][c]      640KB

// packed f32x2 helpers (sm_100+)
__device__ __forceinline__ unsigned long long pack2(float lo, float hi) {
    unsigned long long r;
    asm("mov.b64 %0, {%1,%2};" : "=l"(r) : "f"(lo), "f"(hi));
    return r;
}
__device__ __forceinline__ void unpack2(float& lo, float& hi, unsigned long long v) {
    asm("mov.b64 {%0,%1}, %2;" : "=f"(lo), "=f"(hi) : "l"(v));
}
#define FMA2(d, a, b, c) asm("fma.rn.f32x2 %0, %1, %2, %3;" : "=l"(d) : "l"(a), "l"(b), "l"(c))

// ---------------------------------------------------------------------------
// Kernel 1: Wh = x @ W ; D[i,y,dy] = sum_{x,c} Wh[i,y,x,c] * a[dy*256+x*16+c]
// grid 100 (i), block 256 (pixel)
// ---------------------------------------------------------------------------
__global__ __launch_bounds__(256) void k_wh_d(const float* __restrict__ x,
                                              const float* __restrict__ W,
                                              const float* __restrict__ a)
{
    __shared__ float W_s[FIN * FOUT];
    __shared__ float a_s[512];

    const int i = blockIdx.x;
    const int p = threadIdx.x;

    if (p < FIN * FOUT) W_s[p] = W[p];
    a_s[p]       = a[p];
    a_s[p + 256] = a[p + 256];
    __syncthreads();

    const float4* xp = reinterpret_cast<const float4*>(x) + (size_t)(i * PIX + p) * 2;
    float4 x0 = xp[0];
    float4 x1 = xp[1];
    float xv[8] = {x0.x, x0.y, x0.z, x0.w, x1.x, x1.y, x1.z, x1.w};

    float wh[FOUT];
#pragma unroll
    for (int c = 0; c < FOUT; ++c) {
        float s = 0.f;
#pragma unroll
        for (int k = 0; k < FIN; ++k) s += xv[k] * W_s[k * FOUT + c];
        wh[c] = s;
    }

    float4* whp = reinterpret_cast<float4*>(g_Wh) + (size_t)(i * PIX + p) * 4;
    whp[0] = make_float4(wh[0],  wh[1],  wh[2],  wh[3]);
    whp[1] = make_float4(wh[4],  wh[5],  wh[6],  wh[7]);
    whp[2] = make_float4(wh[8],  wh[9],  wh[10], wh[11]);
    whp[3] = make_float4(wh[12], wh[13], wh[14], wh[15]);

    const int xx = p & 15;
    float pd0 = 0.f, pd1 = 0.f;
#pragma unroll
    for (int c = 0; c < FOUT; ++c) {
        pd0 += wh[c] * a_s[xx * 16 + c];
        pd1 += wh[c] * a_s[256 + xx * 16 + c];
    }
#pragma unroll
    for (int off = 8; off >= 1; off >>= 1) {
        pd0 += __shfl_xor_sync(0xffffffffu, pd0, off, 16);
        pd1 += __shfl_xor_sync(0xffffffffu, pd1, off, 16);
    }
    if (xx == 0) {
        const int y = p >> 4;
        g_D[i * 32 + 2 * y]     = pd0;
        g_D[i * 32 + 2 * y + 1] = pd1;
    }
}

// ---------------------------------------------------------------------------
// Kernel 2: e -> leakyrelu -> mask -> softmax over j -> g_att[i][j][c]
// grid 100 (i), block 512: warp = channel c, lanes cover j strided 32
// ---------------------------------------------------------------------------
__global__ __launch_bounds__(512) void k_att(const int* __restrict__ adj)
{
    __shared__ float D_i[32];

    const int i   = blockIdx.x;
    const int tid = threadIdx.x;
    const int c   = tid >> 5;
    const int l   = tid & 31;

    if (tid < 32) D_i[tid] = g_D[i * 32 + tid];
    __syncthreads();

    float ev[4];
    float mx = -3.4e38f;
#pragma unroll
    for (int t = 0; t < 4; ++t) {
        const int j = l + t * 32;
        if (j < N_NODES) {
            float e;
            if (c < 8) {
                const int b = 16 * j + 2 * c;
                e = D_i[(b / 100) * 2] + D_i[((b + 1) / 100) * 2 + 1];
            } else {
                const int r = 2 * c - 16;
                e = g_D[j * 32 + 2 * r] + g_D[j * 32 + 2 * (r + 1) + 1];
            }
            e = (e > 0.f) ? e : ALPHA * e;
            e = (adj[i * N_NODES + j] > 0) ? e : -9e15f;
            ev[t] = e;
            mx = fmaxf(mx, e);
        } else {
            ev[t] = -3.4e38f;
        }
    }
#pragma unroll
    for (int off = 16; off >= 1; off >>= 1)
        mx = fmaxf(mx, __shfl_xor_sync(0xffffffffu, mx, off));

    float s = 0.f;
#pragma unroll
    for (int t = 0; t < 4; ++t) {
        const int j = l + t * 32;
        if (j < N_NODES) {
            ev[t] = __expf(ev[t] - mx);
            s += ev[t];
        }
    }
#pragma unroll
    for (int off = 16; off >= 1; off >>= 1)
        s += __shfl_xor_sync(0xffffffffu, s, off);

    const float inv = 1.0f / s;
#pragma unroll
    for (int t = 0; t < 4; ++t) {
        const int j = l + t * 32;
        if (j < N_NODES)
            g_att[(size_t)i * (N_NODES * FOUT) + j * FOUT + c] = ev[t] * inv;
    }
}

// ---------------------------------------------------------------------------
// Kernel 3: h'[i, pixel, c] = sum_{j=0..99} att[i,j,c] * Wh[j,pixel,c]
// grid (25 i-tiles of 4, 8 pixel-tiles of 32), block 128:
//   warp = c-group, lane = pixel. MLP-8 batched Wh loads, f32x2 FMAs.
// ---------------------------------------------------------------------------
#define TI 4
__global__ __launch_bounds__(128) void k_hprime(float* __restrict__ out)
{
    __shared__ __align__(16) float att_s[TI * N_NODES * FOUT];   // 25.6KB

    const int tid = threadIdx.x;
    const int w   = tid >> 5;
    const int l   = tid & 31;
    const int i0  = blockIdx.x * TI;
    const int p0  = blockIdx.y * 32;

    {
        float4* dst = reinterpret_cast<float4*>(att_s);
        const float4* src = reinterpret_cast<const float4*>(g_att + (size_t)i0 * N_NODES * FOUT);
        for (int q = tid; q < TI * N_NODES * 4; q += 128)
            dst[q] = src[q];
    }
    __syncthreads();

    const int pixel = p0 + l;

    unsigned long long acc0[TI], acc1[TI];
    const unsigned long long z = pack2(0.f, 0.f);
#pragma unroll
    for (int ii = 0; ii < TI; ++ii) { acc0[ii] = z; acc1[ii] = z; }

    const ulonglong2* wh2 = reinterpret_cast<const ulonglong2*>(g_Wh) +
                            (size_t)pixel * 4 + w;
    const ulonglong2* at2 = reinterpret_cast<const ulonglong2*>(att_s);

#pragma unroll 1
    for (int jb = 0; jb < 96; jb += 8) {
        ulonglong2 wb[8];
#pragma unroll
        for (int u = 0; u < 8; ++u)
            wb[u] = wh2[(size_t)(jb + u) * (PIX * 4)];
#pragma unroll
        for (int u = 0; u < 8; ++u) {
#pragma unroll
            for (int ii = 0; ii < TI; ++ii) {
                const ulonglong2 ap = at2[(ii * N_NODES + jb + u) * 4 + w];
                FMA2(acc0[ii], ap.x, wb[u].x, acc0[ii]);
                FMA2(acc1[ii], ap.y, wb[u].y, acc1[ii]);
            }
        }
    }
    {   // tail j = 96..99
        ulonglong2 wb[4];
#pragma unroll
        for (int u = 0; u < 4; ++u)
            wb[u] = wh2[(size_t)(96 + u) * (PIX * 4)];
#pragma unroll
        for (int u = 0; u < 4; ++u) {
#pragma unroll
            for (int ii = 0; ii < TI; ++ii) {
                const ulonglong2 ap = at2[(ii * N_NODES + 96 + u) * 4 + w];
                FMA2(acc0[ii], ap.x, wb[u].x, acc0[ii]);
                FMA2(acc1[ii], ap.y, wb[u].y, acc1[ii]);
            }
        }
    }

#pragma unroll
    for (int ii = 0; ii < TI; ++ii) {
        float f0, f1, f2, f3;
        unpack2(f0, f1, acc0[ii]);
        unpack2(f2, f3, acc1[ii]);
        reinterpret_cast<float4*>(out)[((i0 + ii) * PIX + pixel) * 4 + w] =
            make_float4(f0, f1, f2, f3);
    }
}

// ---------------------------------------------------------------------------
extern "C" void kernel_launch(void* const* d_in, const int* in_sizes, int n_in,
                              void* d_out, int out_size)
{
    const float* x   = (const float*)d_in[0];
    const int*   adj = (const int*)d_in[1];
    const float* W   = (const float*)d_in[2];
    const float* a   = (const float*)d_in[3];
    float* out = (float*)d_out;

    k_wh_d<<<N_NODES, 256>>>(x, W, a);
    k_att<<<N_NODES, 512>>>(adj);
    dim3 g3(N_NODES / TI, PIX / 32);
    k_hprime<<<g3, 128>>>(out);
}